// round 6
// baseline (speedup 1.0000x reference)
#include <cuda_runtime.h>
#include <cstdint>

#define OHW      16384          // input plane (128*128)
#define NQ       65536          // output plane (256*256)
#define NPLANES  1024           // B*C
#define NTAPS    262144         // OHW * K * P
#define ROW      8              // padded slots per output pixel
#define G        3              // planes per CTA in gather kernel
#define MAIN_THREADS 512
#define MAIN_CTAS    342        // ceil(1024/3)
#define SMEM_BYTES   (G * OHW * 4)

// Inverted-map scratch (device globals: allocation-free)
__device__ uint2 g_rows[NQ * ROW];   // 4 MB: {w_bits, s | k<<14}, zero-padded
__device__ int   g_cnt[NQ];
__device__ int   g_spill_n;
__device__ int4  g_spill[NTAPS];     // {q, s|k<<14, w_bits, 0} overflow (worst case)

__global__ void k_zero()
{
    int i = blockIdx.x * blockDim.x + threadIdx.x;
    int stride = gridDim.x * blockDim.x;
    uint4* rows4 = reinterpret_cast<uint4*>(g_rows);
    const int NR4 = NQ * ROW / 2;                 // 262144 uint4
    for (int j = i; j < NR4; j += stride) rows4[j] = make_uint4(0u, 0u, 0u, 0u);
    int4* cnt4 = reinterpret_cast<int4*>(g_cnt);
    for (int j = i; j < NQ / 4; j += stride) cnt4[j] = make_int4(0, 0, 0, 0);
    if (i == 0) g_spill_n = 0;
}

__global__ void k_build(const int* __restrict__ smap, const float* __restrict__ wts)
{
    int i = blockIdx.x * blockDim.x + threadIdx.x;
    if (i >= NTAPS) return;
    int q = smap[i];
    unsigned s = (unsigned)(i >> 4);              // tap layout: (s, k, p)
    unsigned k = (unsigned)((i >> 2) & 3);
    unsigned sk = s | (k << 14);
    unsigned wb = __float_as_uint(wts[i]);
    int r = atomicAdd(&g_cnt[q], 1);
    if (r < ROW) {
        g_rows[q * ROW + r] = make_uint2(wb, sk);
    } else {
        int j = atomicAdd(&g_spill_n, 1);
        g_spill[j] = make_int4(q, (int)sk, (int)wb, 0);
    }
}

__global__ void __launch_bounds__(MAIN_THREADS)
k_main(const float* __restrict__ x, const int* __restrict__ mask, float* __restrict__ out)
{
    extern __shared__ unsigned sm[];              // G planes: x with mask in low 2 mantissa bits
    int tid = threadIdx.x;
    int p0 = blockIdx.x * G;
    int gmax = NPLANES - p0; if (gmax > G) gmax = G;

    for (int g = 0; g < G; g++) {
        if (g < gmax) {
            const float* xp = x    + (size_t)(p0 + g) * OHW;
            const int*   mp = mask + (size_t)(p0 + g) * OHW;
            for (int s = tid; s < OHW; s += MAIN_THREADS)
                sm[g * OHW + s] = (__float_as_uint(xp[s]) & ~3u) | ((unsigned)mp[s] & 3u);
        } else {
            for (int s = tid; s < OHW; s += MAIN_THREADS)
                sm[g * OHW + s] = 0u;             // tail CTA: benign zeros
        }
    }
    __syncthreads();

    for (int q = tid; q < NQ; q += MAIN_THREADS) {
        const uint4* row = reinterpret_cast<const uint4*>(g_rows + (size_t)q * ROW);
        uint4 r0 = row[0], r1 = row[1], r2 = row[2], r3 = row[3];
        float a0 = 0.f, a1 = 0.f, a2 = 0.f;

        // Branch-free: padding slots have w==0 -> contribute 0.
#define ENT(wb, skv) do {                                          \
        unsigned sk_ = (skv);                                      \
        unsigned s_  = sk_ & 0x3FFFu;                              \
        unsigned k_  = (sk_ >> 14) & 3u;                           \
        float    w_  = __uint_as_float(wb);                        \
        unsigned x0 = sm[s_];                                      \
        unsigned x1 = sm[OHW + s_];                                \
        unsigned x2 = sm[2 * OHW + s_];                            \
        a0 += ((x0 & 3u) == k_) ? w_ * __uint_as_float(x0) : 0.f;  \
        a1 += ((x1 & 3u) == k_) ? w_ * __uint_as_float(x1) : 0.f;  \
        a2 += ((x2 & 3u) == k_) ? w_ * __uint_as_float(x2) : 0.f;  \
    } while (0)

        ENT(r0.x, r0.y); ENT(r0.z, r0.w);
        ENT(r1.x, r1.y); ENT(r1.z, r1.w);
        ENT(r2.x, r2.y); ENT(r2.z, r2.w);
        ENT(r3.x, r3.y); ENT(r3.z, r3.w);
#undef ENT

        out[(size_t)p0 * NQ + q] = a0;
        if (gmax > 1) out[(size_t)(p0 + 1) * NQ + q] = a1;
        if (gmax > 2) out[(size_t)(p0 + 2) * NQ + q] = a2;
    }
}

__global__ void k_spill(const float* __restrict__ x, const int* __restrict__ mask,
                        float* __restrict__ out)
{
    int plane = blockIdx.x;
    int n = g_spill_n;                            // ~2K expected
    const float* xp = x    + (size_t)plane * OHW;
    const int*   mp = mask + (size_t)plane * OHW;
    float* op = out + (size_t)plane * NQ;
    for (int j = threadIdx.x; j < n; j += blockDim.x) {
        int4 e = g_spill[j];
        int s = e.y & 0x3FFF;
        int k = (e.y >> 14) & 3;
        if (mp[s] == k)
            atomicAdd(op + e.x, __int_as_float(e.z) * xp[s]);
    }
}

extern "C" void kernel_launch(void* const* d_in, const int* in_sizes, int n_in,
                              void* d_out, int out_size)
{
    const float* x    = (const float*)d_in[0];
    const int*   mask = (const int*)d_in[1];
    const int*   smap = (const int*)d_in[2];
    const float* wts  = (const float*)d_in[3];
    float* out = (float*)d_out;

    cudaFuncSetAttribute(k_main, cudaFuncAttributeMaxDynamicSharedMemorySize, SMEM_BYTES);

    k_zero<<<256, 256>>>();
    k_build<<<NTAPS / 256, 256>>>(smap, wts);
    k_main<<<MAIN_CTAS, MAIN_THREADS, SMEM_BYTES>>>(x, mask, out);
    k_spill<<<NPLANES, 128>>>(x, mask, out);
}

// round 7
// speedup vs baseline: 1.0036x; 1.0036x over previous
#include <cuda_runtime.h>
#include <cstdint>

#define OHW      16384          // input plane (128*128)
#define NQ       65536          // output plane (256*256)
#define NPLANES  1024           // B*C
#define NTAPS    262144         // OHW * K * P
#define ROW      8              // padded slots per output pixel
#define G        3              // planes per CTA in gather kernel
#define MAIN_THREADS 512
#define MAIN_CTAS    342        // ceil(1024/3)
#define SMEM_BYTES   (G * OHW * 4)

// Inverted-map scratch (device globals: allocation-free)
__device__ uint2 g_rows[NQ * ROW];   // 4 MB: {w_bits, s | k<<14}, zero-padded
__device__ int   g_cnt[NQ];
__device__ int   g_spill_n;
__device__ int4  g_spill[NTAPS];     // {q, s|k<<14, w_bits, 0} overflow (worst case)

__global__ void k_zero()
{
    int i = blockIdx.x * blockDim.x + threadIdx.x;
    int stride = gridDim.x * blockDim.x;
    uint4* rows4 = reinterpret_cast<uint4*>(g_rows);
    const int NR4 = NQ * ROW / 2;                 // 262144 uint4
    for (int j = i; j < NR4; j += stride) rows4[j] = make_uint4(0u, 0u, 0u, 0u);
    int4* cnt4 = reinterpret_cast<int4*>(g_cnt);
    for (int j = i; j < NQ / 4; j += stride) cnt4[j] = make_int4(0, 0, 0, 0);
    if (i == 0) g_spill_n = 0;
}

__global__ void k_build(const int* __restrict__ smap, const float* __restrict__ wts)
{
    int i = blockIdx.x * blockDim.x + threadIdx.x;
    if (i >= NTAPS) return;
    int q = smap[i];
    unsigned s = (unsigned)(i >> 4);              // tap layout: (s, k, p)
    unsigned k = (unsigned)((i >> 2) & 3);
    unsigned sk = s | (k << 14);
    unsigned wb = __float_as_uint(wts[i]);
    int r = atomicAdd(&g_cnt[q], 1);
    if (r < ROW) {
        g_rows[q * ROW + r] = make_uint2(wb, sk);
    } else {
        int j = atomicAdd(&g_spill_n, 1);
        g_spill[j] = make_int4(q, (int)sk, (int)wb, 0);
    }
}

__global__ void __launch_bounds__(MAIN_THREADS)
k_main(const float* __restrict__ x, const int* __restrict__ mask, float* __restrict__ out)
{
    extern __shared__ unsigned sm[];              // G planes: x with mask in low 2 mantissa bits
    int tid = threadIdx.x;
    int p0 = blockIdx.x * G;
    int gmax = NPLANES - p0; if (gmax > G) gmax = G;

    for (int g = 0; g < G; g++) {
        if (g < gmax) {
            const float* xp = x    + (size_t)(p0 + g) * OHW;
            const int*   mp = mask + (size_t)(p0 + g) * OHW;
            for (int s = tid; s < OHW; s += MAIN_THREADS)
                sm[g * OHW + s] = (__float_as_uint(xp[s]) & ~3u) | ((unsigned)mp[s] & 3u);
        } else {
            for (int s = tid; s < OHW; s += MAIN_THREADS)
                sm[g * OHW + s] = 0u;             // tail CTA: benign zeros
        }
    }
    __syncthreads();

    for (int q = tid; q < NQ; q += MAIN_THREADS) {
        const uint4* row = reinterpret_cast<const uint4*>(g_rows + (size_t)q * ROW);
        uint4 r0 = row[0], r1 = row[1], r2 = row[2], r3 = row[3];
        float a0 = 0.f, a1 = 0.f, a2 = 0.f;

        // Branch-free: padding slots have w==0 -> contribute 0.
#define ENT(wb, skv) do {                                          \
        unsigned sk_ = (skv);                                      \
        unsigned s_  = sk_ & 0x3FFFu;                              \
        unsigned k_  = (sk_ >> 14) & 3u;                           \
        float    w_  = __uint_as_float(wb);                        \
        unsigned x0 = sm[s_];                                      \
        unsigned x1 = sm[OHW + s_];                                \
        unsigned x2 = sm[2 * OHW + s_];                            \
        a0 += ((x0 & 3u) == k_) ? w_ * __uint_as_float(x0) : 0.f;  \
        a1 += ((x1 & 3u) == k_) ? w_ * __uint_as_float(x1) : 0.f;  \
        a2 += ((x2 & 3u) == k_) ? w_ * __uint_as_float(x2) : 0.f;  \
    } while (0)

        ENT(r0.x, r0.y); ENT(r0.z, r0.w);
        ENT(r1.x, r1.y); ENT(r1.z, r1.w);
        ENT(r2.x, r2.y); ENT(r2.z, r2.w);
        ENT(r3.x, r3.y); ENT(r3.z, r3.w);
#undef ENT

        out[(size_t)p0 * NQ + q] = a0;
        if (gmax > 1) out[(size_t)(p0 + 1) * NQ + q] = a1;
        if (gmax > 2) out[(size_t)(p0 + 2) * NQ + q] = a2;
    }
}

__global__ void k_spill(const float* __restrict__ x, const int* __restrict__ mask,
                        float* __restrict__ out)
{
    int plane = blockIdx.x;
    int n = g_spill_n;                            // ~2K expected
    const float* xp = x    + (size_t)plane * OHW;
    const int*   mp = mask + (size_t)plane * OHW;
    float* op = out + (size_t)plane * NQ;
    for (int j = threadIdx.x; j < n; j += blockDim.x) {
        int4 e = g_spill[j];
        int s = e.y & 0x3FFF;
        int k = (e.y >> 14) & 3;
        if (mp[s] == k)
            atomicAdd(op + e.x, __int_as_float(e.z) * xp[s]);
    }
}

extern "C" void kernel_launch(void* const* d_in, const int* in_sizes, int n_in,
                              void* d_out, int out_size)
{
    const float* x    = (const float*)d_in[0];
    const int*   mask = (const int*)d_in[1];
    const int*   smap = (const int*)d_in[2];
    const float* wts  = (const float*)d_in[3];
    float* out = (float*)d_out;

    cudaFuncSetAttribute(k_main, cudaFuncAttributeMaxDynamicSharedMemorySize, SMEM_BYTES);

    k_zero<<<256, 256>>>();
    k_build<<<NTAPS / 256, 256>>>(smap, wts);
    k_main<<<MAIN_CTAS, MAIN_THREADS, SMEM_BYTES>>>(x, mask, out);
    k_spill<<<NPLANES, 128>>>(x, mask, out);
}

// round 8
// speedup vs baseline: 1.5652x; 1.5596x over previous
#include <cuda_runtime.h>
#include <cuda_fp16.h>
#include <cstdint>

#define OHW      16384          // input plane (128*128)
#define NQ       65536          // output plane (256*256)
#define NPLANES  1024           // B*C
#define NTAPS    262144         // OHW * K * P
#define ROW      8              // padded slots per output pixel
#define G        2              // planes per CTA in gather kernel
#define MAIN_THREADS 1024
#define MAIN_CTAS    (NPLANES / G)        // 512
#define SMEM_BYTES   (G * OHW * 4)        // 128 KB

// Inverted-map scratch (device globals: allocation-free)
// entry: [31:16] w as fp16 bits, [15:14] k, [13:0] s
__device__ unsigned g_tab[NQ * ROW];   // 2 MB, zero-padded
__device__ int      g_cnt[NQ];
__device__ int      g_spill_n;
__device__ int4     g_spill[NTAPS];    // {q, s|k<<14, w_fp32_bits, 0}

__global__ void k_zero()
{
    int i = blockIdx.x * blockDim.x + threadIdx.x;
    int stride = gridDim.x * blockDim.x;
    uint4* t4 = reinterpret_cast<uint4*>(g_tab);
    const int NT4 = NQ * ROW / 4;                 // 131072
    for (int j = i; j < NT4; j += stride) t4[j] = make_uint4(0u, 0u, 0u, 0u);
    int4* c4 = reinterpret_cast<int4*>(g_cnt);
    for (int j = i; j < NQ / 4; j += stride) c4[j] = make_int4(0, 0, 0, 0);
    if (i == 0) g_spill_n = 0;
}

__global__ void k_build(const int* __restrict__ smap, const float* __restrict__ wts)
{
    int i = blockIdx.x * blockDim.x + threadIdx.x;
    if (i >= NTAPS) return;
    int q = smap[i];
    unsigned s = (unsigned)(i >> 4);              // tap layout: (s, k, p)
    unsigned k = (unsigned)((i >> 2) & 3);
    unsigned sk = s | (k << 14);
    float w = wts[i];
    int r = atomicAdd(&g_cnt[q], 1);
    if (r < ROW) {
        unsigned hw = (unsigned)__half_as_ushort(__float2half_rn(w));
        g_tab[q * ROW + r] = (hw << 16) | sk;
    } else {
        int j = atomicAdd(&g_spill_n, 1);
        g_spill[j] = make_int4(q, (int)sk, __float_as_int(w), 0);
    }
}

__global__ void __launch_bounds__(MAIN_THREADS)
k_main(const float* __restrict__ x, const int* __restrict__ mask, float* __restrict__ out)
{
    extern __shared__ unsigned sm[];              // 2 planes, mask in low 2 mantissa bits
    int tid = threadIdx.x;
    int p0 = blockIdx.x * G;

    const float* x0 = x    + (size_t)p0 * OHW;
    const float* x1 = x0 + OHW;
    const int*   m0 = mask + (size_t)p0 * OHW;
    const int*   m1 = m0 + OHW;
    for (int s = tid; s < OHW; s += MAIN_THREADS) {
        sm[s]       = (__float_as_uint(__ldg(x0 + s)) & ~3u) | ((unsigned)__ldg(m0 + s) & 3u);
        sm[OHW + s] = (__float_as_uint(__ldg(x1 + s)) & ~3u) | ((unsigned)__ldg(m1 + s) & 3u);
    }
    __syncthreads();

    float* o0 = out + (size_t)p0 * NQ;
    float* o1 = o0 + NQ;

    #pragma unroll 1
    for (int i = 0; i < NQ / MAIN_THREADS; i++) {
        int q = tid + i * MAIN_THREADS;
        int cnt = __ldg(g_cnt + q);
        if (cnt > ROW) cnt = ROW;
        const uint4* row = reinterpret_cast<const uint4*>(g_tab + (size_t)q * ROW);
        uint4 rlo = __ldg(row);
        uint4 rhi = make_uint4(0u, 0u, 0u, 0u);
        if (cnt > 4) rhi = __ldg(row + 1);

        unsigned e[8] = { rlo.x, rlo.y, rlo.z, rlo.w, rhi.x, rhi.y, rhi.z, rhi.w };
        float a0 = 0.f, a1 = 0.f;
        #pragma unroll
        for (int r = 0; r < ROW; r++) {
            if (r < cnt) {
                unsigned ee = e[r];
                unsigned s_ = ee & 0x3FFFu;
                unsigned k_ = (ee >> 14) & 3u;
                float w = __half2float(__ushort_as_half((unsigned short)(ee >> 16)));
                unsigned v0 = sm[s_];
                unsigned v1 = sm[OHW + s_];
                if ((v0 & 3u) == k_) a0 += w * __uint_as_float(v0);
                if ((v1 & 3u) == k_) a1 += w * __uint_as_float(v1);
            }
        }
        o0[q] = a0;
        o1[q] = a1;
    }

    // Spill pass: rare overflow entries, planes already in SMEM.
    __syncthreads();                              // order plain stores before atomics
    int n = g_spill_n;
    for (int j = tid; j < n; j += MAIN_THREADS) {
        int4 e = g_spill[j];
        unsigned sk = (unsigned)e.y;
        unsigned s_ = sk & 0x3FFFu;
        unsigned k_ = (sk >> 14) & 3u;
        float w = __int_as_float(e.z);
        unsigned v0 = sm[s_];
        unsigned v1 = sm[OHW + s_];
        if ((v0 & 3u) == k_) atomicAdd(o0 + e.x, w * __uint_as_float(v0));
        if ((v1 & 3u) == k_) atomicAdd(o1 + e.x, w * __uint_as_float(v1));
    }
}

extern "C" void kernel_launch(void* const* d_in, const int* in_sizes, int n_in,
                              void* d_out, int out_size)
{
    const float* x    = (const float*)d_in[0];
    const int*   mask = (const int*)d_in[1];
    const int*   smap = (const int*)d_in[2];
    const float* wts  = (const float*)d_in[3];
    float* out = (float*)d_out;

    cudaFuncSetAttribute(k_main, cudaFuncAttributeMaxDynamicSharedMemorySize, SMEM_BYTES);

    k_zero<<<256, 256>>>();
    k_build<<<NTAPS / 256, 256>>>(smap, wts);
    k_main<<<MAIN_CTAS, MAIN_THREADS, SMEM_BYTES>>>(x, mask, out);
}

// round 9
// speedup vs baseline: 1.6964x; 1.0838x over previous
#include <cuda_runtime.h>
#include <cuda_fp16.h>
#include <cstdint>

#define OHW      16384          // input plane (128*128)
#define NQ       65536          // output plane (256*256)
#define NPLANES  1024           // B*C
#define NTAPS    262144         // OHW * K * P
#define ROW      8              // padded slots per output pixel
#define G        3              // planes per CTA in gather kernel
#define MAIN_THREADS 1024
#define MAIN_CTAS    ((NPLANES + G - 1) / G)   // 342
#define SMEM_BYTES   (G * OHW * 4)             // 192 KB
#define NITER        (NQ / MAIN_THREADS)       // 64

// Inverted-map scratch (device globals: allocation-free)
// entry: [31:16] w as fp16 bits, [15:14] k, [13:0] s   (0 == padding: w=0,s=0)
__device__ unsigned g_tab[NQ * ROW];   // 2 MB, zero-padded
__device__ int      g_cnt[NQ];
__device__ int      g_spill_n;
__device__ int4     g_spill[NTAPS];    // {q, s|k<<14, w_fp32_bits, 0}

__global__ void k_zero()
{
    int i = blockIdx.x * blockDim.x + threadIdx.x;
    int stride = gridDim.x * blockDim.x;
    uint4* t4 = reinterpret_cast<uint4*>(g_tab);
    const int NT4 = NQ * ROW / 4;                 // 131072
    for (int j = i; j < NT4; j += stride) t4[j] = make_uint4(0u, 0u, 0u, 0u);
    int4* c4 = reinterpret_cast<int4*>(g_cnt);
    for (int j = i; j < NQ / 4; j += stride) c4[j] = make_int4(0, 0, 0, 0);
    if (i == 0) g_spill_n = 0;
}

__global__ void k_build(const int* __restrict__ smap, const float* __restrict__ wts)
{
    int i = blockIdx.x * blockDim.x + threadIdx.x;
    if (i >= NTAPS) return;
    int q = smap[i];
    unsigned s = (unsigned)(i >> 4);              // tap layout: (s, k, p)
    unsigned k = (unsigned)((i >> 2) & 3);
    unsigned sk = s | (k << 14);
    float w = wts[i];
    int r = atomicAdd(&g_cnt[q], 1);
    if (r < ROW) {
        unsigned hw = (unsigned)__half_as_ushort(__float2half_rn(w));
        g_tab[q * ROW + r] = (hw << 16) | sk;
    } else {
        int j = atomicAdd(&g_spill_n, 1);
        g_spill[j] = make_int4(q, (int)sk, __float_as_int(w), 0);
    }
}

__global__ void __launch_bounds__(MAIN_THREADS)
k_main(const float* __restrict__ x, const int* __restrict__ mask, float* __restrict__ out)
{
    extern __shared__ unsigned sm[];              // G planes, mask in low 2 mantissa bits
    int tid = threadIdx.x;
    int p0 = blockIdx.x * G;
    int gmax = NPLANES - p0; if (gmax > G) gmax = G;

    // Stage planes into SMEM (absent tail planes -> zeros, benign)
    for (int g = 0; g < G; g++) {
        unsigned* smg = sm + g * OHW;
        if (g < gmax) {
            const float* xp = x    + (size_t)(p0 + g) * OHW;
            const int*   mp = mask + (size_t)(p0 + g) * OHW;
            for (int s = tid; s < OHW; s += MAIN_THREADS)
                smg[s] = (__float_as_uint(__ldg(xp + s)) & ~3u) | ((unsigned)__ldg(mp + s) & 3u);
        } else {
            for (int s = tid; s < OHW; s += MAIN_THREADS) smg[s] = 0u;
        }
    }
    __syncthreads();

    float* o0 = out + (size_t)p0 * NQ;
    float* o1 = o0 + NQ;
    float* o2 = o1 + NQ;

    const uint4* tab4 = reinterpret_cast<const uint4*>(g_tab);

    int q = tid;
    uint4 rlo = __ldg(tab4 + 2 * q);
    uint4 rhi = __ldg(tab4 + 2 * q + 1);

    #pragma unroll 1
    for (int i = 0; i < NITER; i++) {
        // Prefetch next row pair (uniform branch)
        uint4 nlo, nhi;
        int qn = q + MAIN_THREADS;
        if (i < NITER - 1) {
            nlo = __ldg(tab4 + 2 * qn);
            nhi = __ldg(tab4 + 2 * qn + 1);
        }

        unsigned e[8] = { rlo.x, rlo.y, rlo.z, rlo.w, rhi.x, rhi.y, rhi.z, rhi.w };
        float a0 = 0.f, a1 = 0.f, a2 = 0.f;
        #pragma unroll
        for (int r = 0; r < ROW; r++) {
            unsigned ee = e[r];
            unsigned s_ = ee & 0x3FFFu;
            unsigned k_ = (ee >> 14) & 3u;
            float w = __half2float(__ushort_as_half((unsigned short)(ee >> 16)));
            unsigned v0 = sm[s_];
            unsigned v1 = sm[OHW + s_];
            unsigned v2 = sm[2 * OHW + s_];
            a0 += ((v0 & 3u) == k_) ? w * __uint_as_float(v0) : 0.f;
            a1 += ((v1 & 3u) == k_) ? w * __uint_as_float(v1) : 0.f;
            a2 += ((v2 & 3u) == k_) ? w * __uint_as_float(v2) : 0.f;
        }
        o0[q] = a0;
        if (gmax > 1) o1[q] = a1;
        if (gmax > 2) o2[q] = a2;

        rlo = nlo; rhi = nhi; q = qn;
    }

    // Spill pass: rare overflow entries (P(cnt>8) ~ 2%), planes already in SMEM.
    __syncthreads();                              // order plain stores before atomics
    int n = g_spill_n;
    for (int j = tid; j < n; j += MAIN_THREADS) {
        int4 e = g_spill[j];
        unsigned sk = (unsigned)e.y;
        unsigned s_ = sk & 0x3FFFu;
        unsigned k_ = (sk >> 14) & 3u;
        float w = __int_as_float(e.z);
        unsigned v0 = sm[s_];
        unsigned v1 = sm[OHW + s_];
        unsigned v2 = sm[2 * OHW + s_];
        if ((v0 & 3u) == k_)              atomicAdd(o0 + e.x, w * __uint_as_float(v0));
        if (gmax > 1 && (v1 & 3u) == k_)  atomicAdd(o1 + e.x, w * __uint_as_float(v1));
        if (gmax > 2 && (v2 & 3u) == k_)  atomicAdd(o2 + e.x, w * __uint_as_float(v2));
    }
}

extern "C" void kernel_launch(void* const* d_in, const int* in_sizes, int n_in,
                              void* d_out, int out_size)
{
    const float* x    = (const float*)d_in[0];
    const int*   mask = (const int*)d_in[1];
    const int*   smap = (const int*)d_in[2];
    const float* wts  = (const float*)d_in[3];
    float* out = (float*)d_out;

    cudaFuncSetAttribute(k_main, cudaFuncAttributeMaxDynamicSharedMemorySize, SMEM_BYTES);

    k_zero<<<256, 256>>>();
    k_build<<<NTAPS / 256, 256>>>(smap, wts);
    k_main<<<MAIN_CTAS, MAIN_THREADS, SMEM_BYTES>>>(x, mask, out);
}

// round 11
// speedup vs baseline: 1.7081x; 1.0069x over previous
#include <cuda_runtime.h>
#include <cuda_fp16.h>
#include <cstdint>

#define OHW      16384          // input plane (128*128)
#define NQ       65536          // output plane (256*256)
#define NPLANES  1024           // B*C
#define NTAPS    262144         // OHW * K * P
#define ROW      8              // padded slots per output pixel
#define G        3              // planes per CTA in gather kernel
#define MAIN_THREADS 1024
#define MAIN_CTAS    ((NPLANES + G - 1) / G)   // 342
#define SMEM_BYTES   (OHW * 8)                 // 128 KB: uint2 per input pixel
#define NITER        (NQ / MAIN_THREADS)       // 64

// Inverted-map scratch (device globals: allocation-free)
// entry: [31:16] w as fp16 bits, [15:14] k, [13:0] s   (0 == padding: w=0,s=0)
__device__ unsigned g_tab[NQ * ROW];   // 2 MB, zero-padded
__device__ int      g_cnt[NQ];
__device__ int      g_spill_n;
__device__ int4     g_spill[NTAPS];    // {q, s|k<<14, w_fp32_bits, 0}

__global__ void k_zero()
{
    int i = blockIdx.x * blockDim.x + threadIdx.x;
    int stride = gridDim.x * blockDim.x;
    uint4* t4 = reinterpret_cast<uint4*>(g_tab);
    const int NT4 = NQ * ROW / 4;                 // 131072
    for (int j = i; j < NT4; j += stride) t4[j] = make_uint4(0u, 0u, 0u, 0u);
    int4* c4 = reinterpret_cast<int4*>(g_cnt);
    for (int j = i; j < NQ / 4; j += stride) c4[j] = make_int4(0, 0, 0, 0);
    if (i == 0) g_spill_n = 0;
}

__global__ void k_build(const int* __restrict__ smap, const float* __restrict__ wts)
{
    int i = blockIdx.x * blockDim.x + threadIdx.x;
    if (i >= NTAPS) return;
    int q = smap[i];
    unsigned s = (unsigned)(i >> 4);              // tap layout: (s, k, p)
    unsigned k = (unsigned)((i >> 2) & 3);
    unsigned sk = s | (k << 14);
    float w = wts[i];
    int r = atomicAdd(&g_cnt[q], 1);
    if (r < ROW) {
        unsigned hw = (unsigned)__half_as_ushort(__float2half_rn(w));
        g_tab[q * ROW + r] = (hw << 16) | sk;
    } else {
        int j = atomicAdd(&g_spill_n, 1);
        g_spill[j] = make_int4(q, (int)sk, __float_as_int(w), 0);
    }
}

__global__ void __launch_bounds__(MAIN_THREADS)
k_main(const float* __restrict__ x, const int* __restrict__ mask, float* __restrict__ out)
{
    // One uint2 record per input pixel s:
    //   .x = x0_fp16 | x1_fp16<<16
    //   .y = x2_fp16 | (m0 | m1<<2 | m2<<4) << 16    (each m is 2 bits)
    extern __shared__ uint2 smv[];
    int tid = threadIdx.x;
    int p0 = blockIdx.x * G;
    int gmax = NPLANES - p0; if (gmax > G) gmax = G;

    {
        const float* xp0 = x    + (size_t)p0 * OHW;
        const int*   mp0 = mask + (size_t)p0 * OHW;
        for (int s = tid; s < OHW; s += MAIN_THREADS) {
            float xv0 = __ldg(xp0 + s);
            unsigned mm0 = (unsigned)__ldg(mp0 + s) & 3u;
            // Absent planes: x=0 so any phantom match contributes w*0 = 0.
            float xv1 = 0.f, xv2 = 0.f;
            unsigned mm1 = 0u, mm2 = 0u;
            if (gmax > 1) { xv1 = __ldg(xp0 + OHW + s);     mm1 = (unsigned)__ldg(mp0 + OHW + s) & 3u; }
            if (gmax > 2) { xv2 = __ldg(xp0 + 2 * OHW + s); mm2 = (unsigned)__ldg(mp0 + 2 * OHW + s) & 3u; }
            unsigned h0 = (unsigned)__half_as_ushort(__float2half_rn(xv0));
            unsigned h1 = (unsigned)__half_as_ushort(__float2half_rn(xv1));
            unsigned h2 = (unsigned)__half_as_ushort(__float2half_rn(xv2));
            unsigned mb = mm0 | (mm1 << 2) | (mm2 << 4);
            smv[s] = make_uint2(h0 | (h1 << 16), h2 | (mb << 16));
        }
    }
    __syncthreads();

    float* o0 = out + (size_t)p0 * NQ;
    float* o1 = o0 + NQ;
    float* o2 = o1 + NQ;

    const uint4* tab4 = reinterpret_cast<const uint4*>(g_tab);

    int q = tid;
    uint4 rlo = __ldg(tab4 + 2 * q);
    uint4 rhi = __ldg(tab4 + 2 * q + 1);

    #pragma unroll 1
    for (int i = 0; i < NITER; i++) {
        uint4 nlo, nhi;
        int qn = q + MAIN_THREADS;
        if (i < NITER - 1) {                      // uniform branch; prefetch next rows
            nlo = __ldg(tab4 + 2 * qn);
            nhi = __ldg(tab4 + 2 * qn + 1);
        }

        unsigned e[8] = { rlo.x, rlo.y, rlo.z, rlo.w, rhi.x, rhi.y, rhi.z, rhi.w };
        float a0 = 0.f, a1 = 0.f, a2 = 0.f;
        #pragma unroll
        for (int r = 0; r < ROW; r++) {
            unsigned ee = e[r];
            unsigned s_ = ee & 0x3FFFu;
            unsigned k_ = (ee >> 14) & 3u;
            float w = __half2float(__ushort_as_half((unsigned short)(ee >> 16)));
            uint2 v = smv[s_];                    // one LDS.64: 3 planes + masks
            unsigned mb = v.y >> 16;
            float2 x01 = __half22float2(*reinterpret_cast<const __half2*>(&v.x));
            float  x2  = __half2float(__ushort_as_half((unsigned short)(v.y & 0xFFFFu)));
            a0 += ((mb        & 3u) == k_) ? w * x01.x : 0.f;
            a1 += (((mb >> 2) & 3u) == k_) ? w * x01.y : 0.f;
            a2 += (((mb >> 4) & 3u) == k_) ? w * x2    : 0.f;
        }
        o0[q] = a0;
        if (gmax > 1) o1[q] = a1;
        if (gmax > 2) o2[q] = a2;

        rlo = nlo; rhi = nhi; q = qn;
    }

    // Spill pass: rare overflow entries, planes already in SMEM.
    // NOTE: atomics MUST be gmax-guarded (tail CTA has <G planes).
    __syncthreads();                              // order plain stores before atomics
    int n = g_spill_n;
    for (int j = tid; j < n; j += MAIN_THREADS) {
        int4 e = g_spill[j];
        unsigned sk = (unsigned)e.y;
        unsigned s_ = sk & 0x3FFFu;
        unsigned k_ = (sk >> 14) & 3u;
        float w = __int_as_float(e.z);
        uint2 v = smv[s_];
        unsigned mb = v.y >> 16;
        float2 x01 = __half22float2(*reinterpret_cast<const __half2*>(&v.x));
        float  x2  = __half2float(__ushort_as_half((unsigned short)(v.y & 0xFFFFu)));
        if ((mb & 3u) == k_)                          atomicAdd(o0 + e.x, w * x01.x);
        if (gmax > 1 && ((mb >> 2) & 3u) == k_)       atomicAdd(o1 + e.x, w * x01.y);
        if (gmax > 2 && ((mb >> 4) & 3u) == k_)       atomicAdd(o2 + e.x, w * x2);
    }
}

extern "C" void kernel_launch(void* const* d_in, const int* in_sizes, int n_in,
                              void* d_out, int out_size)
{
    const float* x    = (const float*)d_in[0];
    const int*   mask = (const int*)d_in[1];
    const int*   smap = (const int*)d_in[2];
    const float* wts  = (const float*)d_in[3];
    float* out = (float*)d_out;

    cudaFuncSetAttribute(k_main, cudaFuncAttributeMaxDynamicSharedMemorySize, SMEM_BYTES);

    k_zero<<<256, 256>>>();
    k_build<<<NTAPS / 256, 256>>>(smap, wts);
    k_main<<<MAIN_CTAS, MAIN_THREADS, SMEM_BYTES>>>(x, mask, out);
}